// round 13
// baseline (speedup 1.0000x reference)
#include <cuda_runtime.h>
#include <cstdint>
#include <cstddef>

#define NN 4096
#define NWm 128          // 4096 bits / 32
#define DD 256
#define EE 65536
#define NBLK 592         // persistent grid: 148 SMs x 4 (co-residency guaranteed)

// ---------------- scratch (device globals; no allocation allowed) -------------
// g_att invariant: all-zero at kernel_launch entry (zeroed at module load;
// k_clean restores the invariant by zeroing exactly the scattered positions).
__device__ __align__(16) float g_att[(size_t)NN * NN];   // structure_M scatter (64MB)
__device__ __align__(16) float g_Z[(size_t)NN * DD];     // normalized embeddings (row-major)
__device__ float    g_p[NN], g_q[NN];           // W projections
__device__ float    g_den[NN];                  // segment sum
__device__ float    g_s[EE];                    // per-edge scratch
__device__ __align__(16) unsigned g_EB[NN * NWm];        // raw edge bitmap
__device__ __align__(16) unsigned g_A1[NN * NWm], g_A2[NN * NWm];
__device__ __align__(16) unsigned g_CM[NN * NWm], g_CMT[NN * NWm];
__device__ float    g_num1[NN], g_deg1[NN], g_scores[NN];
__device__ int      g_mask[NN], g_notkeep[NN], g_keep[NN];
__device__ unsigned g_bmoff[NWm];               // (notkeep && keepcol) column bits
__device__ int      g_is64;                     // edge_index dtype flag
__device__ unsigned g_barcnt, g_barrel;         // software grid barrier state

__device__ __forceinline__ int eidx(const void* ei, int pos) {
    if (g_is64) return (int)((const long long*)ei)[pos];
    return ((const int*)ei)[pos];
}

// warp-collective dot: z[] holds lane's 8 strided dims of row i; j indexes g_Z.
__device__ __forceinline__ float wdot(const float z[8], int j, int lane) {
    const float* zj = g_Z + (size_t)j * DD + lane;
    float d = 0.f;
#pragma unroll
    for (int k = 0; k < 8; k++) d += z[k] * zj[k * 32];
#pragma unroll
    for (int o = 16; o; o >>= 1) d += __shfl_xor_sync(0xffffffffu, d, o);
    return d;
}

// grid-wide barrier (all NBLK blocks co-resident); gen = 1,2,3,...
__device__ __forceinline__ void gbar(unsigned gen) {
    __syncthreads();
    if (threadIdx.x == 0) {
        __threadfence();
        unsigned my = atomicAdd(&g_barcnt, 1u) + 1u;
        if (my == gen * NBLK) atomicExch(&g_barrel, gen);
        while (atomicAdd(&g_barrel, 0u) < gen) __nanosleep(32);
        __threadfence();
    }
    __syncthreads();
}

// ---------------- kernels ----------------------------------------------------

// zero outW, outAdj, outB (192 MB) — no deps; runs on a forked stream
__global__ __launch_bounds__(256) void k_zeroWA(float4* __restrict__ outW,
                                                float4* __restrict__ outAdj,
                                                float4* __restrict__ outB) {
    size_t idx = (size_t)blockIdx.x * blockDim.x + threadIdx.x;   // 4Mi float4
    float4 zv = make_float4(0.f, 0.f, 0.f, 0.f);
    outW[idx] = zv;
    outAdj[idx] = zv;
    outB[idx] = zv;
}

// fused: [0,512) zero bitmaps/scratch, [512,1024) norm+proj, 1024 sniff+barrier reset
__global__ __launch_bounds__(256) void k_pre(const float* __restrict__ emb,
                                             const float* __restrict__ W,
                                             const unsigned* __restrict__ ei_raw) {
    int bx = blockIdx.x;
    if (bx < 512) {
        int idx = bx * 256 + threadIdx.x;          // 0..131071 (NN*NWm/4)
        uint4 zu = make_uint4(0u, 0u, 0u, 0u);
        reinterpret_cast<uint4*>(g_EB)[idx] = zu;
        reinterpret_cast<uint4*>(g_CMT)[idx] = zu;
        if (idx < NN) g_den[idx] = 0.f;
        return;
    }
    if (bx == 1024) {
        if (threadIdx.x >= 32) return;
        int lane = threadIdx.x;
        int nz = 0;
        for (int k = lane; k < 512; k += 32)
            if (ei_raw[2 * k + 1] != 0u) nz++;
#pragma unroll
        for (int o = 16; o; o >>= 1) nz += __shfl_xor_sync(0xffffffffu, nz, o);
        if (lane == 0) {
            g_is64 = (nz == 0) ? 1 : 0;
            g_barcnt = 0u; g_barrel = 0u;          // reset grid barrier per replay
        }
        return;
    }
    int warp = (bx - 512) * 8 + (threadIdx.x >> 5);
    int lane = threadIdx.x & 31;
    const float* er = emb + (size_t)warp * DD;
    float v[8], ss = 0.f, p = 0.f, q = 0.f;
#pragma unroll
    for (int k = 0; k < 8; k++) {
        int d = lane + k * 32;
        float x = er[d];
        v[k] = x; ss += x * x; p += x * W[d]; q += x * W[DD + d];
    }
#pragma unroll
    for (int o = 16; o; o >>= 1) {
        ss += __shfl_xor_sync(0xffffffffu, ss, o);
        p  += __shfl_xor_sync(0xffffffffu, p, o);
        q  += __shfl_xor_sync(0xffffffffu, q, o);
    }
    float inv = 1.0f / fmaxf(sqrtf(ss), 1e-12f);
    float* zr = g_Z + (size_t)warp * DD;
#pragma unroll
    for (int k = 0; k < 8; k++) zr[lane + k * 32] = v[k] * inv;
    if (lane == 0) { g_p[warp] = p; g_q[warp] = q; }
}

// persistent mid-section: edge12 | edge3 | A1 | A2+scores | mask | flags | bits
__global__ __launch_bounds__(128) void k_mid(const void* __restrict__ ei,
                                             const float* __restrict__ bsc,
                                             float* __restrict__ outMask) {
    __shared__ unsigned short nb[NN];
    __shared__ float zi_s[DD];
    __shared__ float rnum[128];
    __shared__ int rdeg[128];
    __shared__ int cnt;

    int t = threadIdx.x;
    int lane = t & 31;
    int wloc = t >> 5;                              // warp in block (0..3)
    int gtid = blockIdx.x * 128 + t;
    int gwarp = blockIdx.x * 4 + wloc;              // 0..2367
    const int NT = NBLK * 128;
    const int NW = NBLK * 4;

    // ---- P0: edge score + exp + segment sum + edge bitmap ----
    float bias = bsc[0];
    for (int e = gtid; e < EE; e += NT) {
        int s = eidx(ei, e), d = eidx(ei, EE + e);
        float x = g_p[s] + g_q[d] + bias;
        x = (x >= 0.f) ? x : 0.01f * x;
        float ex = expf(x);
        g_s[e] = ex;
        atomicAdd(&g_den[s], ex);
        atomicOr(&g_EB[s * NWm + (d >> 5)], 1u << (d & 31));
    }
    gbar(1);

    // ---- P1: att scatter ----
    for (int e = gtid; e < EE; e += NT) {
        int s = eidx(ei, e), d = eidx(ei, EE + e);
        atomicAdd(&g_att[(size_t)s * NN + d], g_s[e] / g_den[s]);
    }
    gbar(2);

    // ---- P2: A1 + num1/deg1 (warp per row) ----
    for (int i = gwarp; i < NN; i += NW) {
        float z[8];
        const float* zi = g_Z + (size_t)i * DD;
#pragma unroll
        for (int k = 0; k < 8; k++) z[k] = zi[lane + 32 * k];
        float num = 0.f;
        int deg = 0;
#pragma unroll
        for (int wq = 0; wq < 4; wq++) {
            int w = lane + wq * 32;
            unsigned myw = g_EB[i * NWm + w];
            if ((i >> 5) == w) myw &= ~(1u << (i & 31));   // offdiag
            unsigned outw = 0u;
            unsigned act = __ballot_sync(0xffffffffu, myw != 0u);
            while (act) {
                int src = __ffs(act) - 1; act &= act - 1;
                unsigned word = __shfl_sync(0xffffffffu, myw, src);
                int wg = src + wq * 32;
                unsigned ob = 0u;
                while (word) {
                    int b = __ffs(word) - 1; word &= word - 1;
                    int j = wg * 32 + b;
                    float fit = wdot(z, j, lane) + g_att[(size_t)i * NN + j];
                    if (fit >= 0.1f) { ob |= 1u << b; num += fit; deg++; }
                }
                if (lane == src) outw = ob;
            }
            g_A1[i * NWm + w] = outw;
        }
        if (lane == 0) { g_num1[i] = num; g_deg1[i] = (float)deg; }
    }
    gbar(3);

    // ---- P3: A2 + CM + CMT scatter + num2/deg2 + final scores (block per row) ----
    for (int i = blockIdx.x; i < NN; i += NBLK) {
        __syncthreads();
        if (t == 0) cnt = 0;
        unsigned rw = g_A1[i * NWm + t];
        for (int k = t; k < DD; k += 128) zi_s[k] = g_Z[(size_t)i * DD + k];
        __syncthreads();
        unsigned tmp = rw;
        while (tmp) {
            int b = __ffs(tmp) - 1; tmp &= tmp - 1;
            int pos = atomicAdd(&cnt, 1);
            nb[pos] = (unsigned short)(t * 32 + b);
        }
        __syncthreads();
        unsigned acc = 0;
        int nc = cnt;
        for (int idx = 0; idx < nc; idx++) acc |= g_A1[(int)nb[idx] * NWm + t];
        unsigned diagm = ((i >> 5) == t) ? (1u << (i & 31)) : 0u;
        unsigned a2 = acc & ~rw & ~diagm;
        g_A2[i * NWm + t] = a2;
        unsigned cm = rw | a2;
        g_CM[i * NWm + t] = cm;
        unsigned word = cm;
        unsigned ibit = 1u << (i & 31);
        int iw = i >> 5;
        while (word) {
            int b = __ffs(word) - 1; word &= word - 1;
            int j = t * 32 + b;
            atomicOr(&g_CMT[j * NWm + iw], ibit);
        }
        // fused num2/deg2 over this thread's a2 word (serial dots vs smem Z_i)
        float num = 0.f;
        int deg = 0;
        unsigned w2 = a2;
        while (w2) {
            int b = __ffs(w2) - 1; w2 &= w2 - 1;
            int j = t * 32 + b;
            const float4* zj = reinterpret_cast<const float4*>(g_Z + (size_t)j * DD);
            float d = 0.f;
#pragma unroll 16
            for (int k = 0; k < 64; k++) {
                float4 v = zj[k];
                d += zi_s[4 * k] * v.x + zi_s[4 * k + 1] * v.y
                   + zi_s[4 * k + 2] * v.z + zi_s[4 * k + 3] * v.w;
            }
            num += d + g_att[(size_t)i * NN + j];
            deg++;
        }
        rnum[t] = num; rdeg[t] = deg;
        __syncthreads();
        for (int o = 64; o; o >>= 1) {
            if (t < o) { rnum[t] += rnum[t + o]; rdeg[t] += rdeg[t + o]; }
            __syncthreads();
        }
        if (t == 0) {
            float d1 = g_deg1[i];
            float s1 = (d1 > 0.f) ? g_num1[i] / d1 : 0.f;
            float s2 = (rdeg[0] > 0) ? rnum[0] / (float)rdeg[0] : 0.f;
            g_scores[i] = 0.5f * (s1 + s2);
        }
    }
    gbar(4);

    // ---- P4: mask (warp per row) ----
    for (int i = gwarp; i < NN; i += NW) {
        float si = g_scores[i];
        bool ok = si > 0.f;
#pragma unroll
        for (int wq = 0; wq < 4; wq++) {
            int w = lane + wq * 32;
            unsigned word = g_A1[i * NWm + w];
            while (word) {
                int b = __ffs(word) - 1; word &= word - 1;
                if (!(si > g_scores[w * 32 + b])) { ok = false; word = 0; }
            }
        }
        ok = __all_sync(0xffffffffu, ok);
        if (lane == 0) { g_mask[i] = ok ? 1 : 0; outMask[i] = ok ? 1.f : 0.f; }
    }
    gbar(5);

    // ---- P5: flags (warp per row) ----
    for (int i = gwarp; i < NN; i += NW) {
        bool red = false;
        int colc = 0;
#pragma unroll
        for (int wq = 0; wq < 4; wq++) {
            int w = lane + wq * 32;
            unsigned cmw = g_CM[i * NWm + w];
            while (cmw) {
                int b = __ffs(cmw) - 1; cmw &= cmw - 1;
                if (g_mask[w * 32 + b]) { red = true; cmw = 0; }
            }
            colc += __popc(g_CMT[i * NWm + w]);
        }
        red = __any_sync(0xffffffffu, red);
#pragma unroll
        for (int o = 16; o; o >>= 1) colc += __shfl_xor_sync(0xffffffffu, colc, o);
        if (lane == 0) {
            bool reduced = red || (colc == 0);
            bool keeping = (!g_mask[i]) && (!reduced);
            g_notkeep[i] = keeping ? 0 : 1;
            g_keep[i]    = reduced ? 0 : 1;
        }
    }
    gbar(6);

    // ---- P6: bmoff bits (warp per 32-node word) ----
    if (gwarp < NWm) {
        int n = gwarp * 32 + lane;
        bool pr = g_notkeep[n] && g_keep[n];
        unsigned b = __ballot_sync(0xffffffffu, pr);
        if (lane == 0) g_bmoff[gwarp] = b;
    }
}

// B = S_w sparse scatter (outB pre-zeroed on forked stream); warp per row
__global__ void k_B(float* __restrict__ outB) {
    int i = (blockIdx.x * blockDim.x + threadIdx.x) >> 5;
    int lane = threadIdx.x & 31;
    if (i >= NN) return;
    float z[8];
    const float* zi = g_Z + (size_t)i * DD;
#pragma unroll
    for (int k = 0; k < 8; k++) z[k] = zi[lane + 32 * k];
#pragma unroll
    for (int wq = 0; wq < 4; wq++) {
        int w = lane + wq * 32;
        unsigned myw = g_CM[i * NWm + w] & g_bmoff[w];
        unsigned act = __ballot_sync(0xffffffffu, myw != 0u);
        while (act) {
            int src = __ffs(act) - 1; act &= act - 1;
            unsigned word = __shfl_sync(0xffffffffu, myw, src);
            int wg = src + wq * 32;
            while (word) {
                int b = __ffs(word) - 1; word &= word - 1;
                int j = wg * 32 + b;
                float fit = wdot(z, j, lane) + g_att[(size_t)i * NN + j];
                if (lane == 0) outB[(size_t)i * NN + j] = fit;
            }
        }
    }
    if (lane == 0) outB[(size_t)i * NN + i] = g_keep[i] ? 1.f : 0.f;
}

// pooled = S_w^T @ emb via CM^T; gathers already-materialized B values
__global__ void k_pooled(float* __restrict__ outP, const float* __restrict__ emb,
                         const float* __restrict__ B) {
    int j = (blockIdx.x * blockDim.x + threadIdx.x) >> 5;
    int lane = threadIdx.x & 31;
    if (j >= NN) return;
    if (!g_keep[j]) {
#pragma unroll
        for (int k = 0; k < 8; k++) outP[(size_t)j * DD + lane + k * 32] = 0.f;
        return;
    }
    float acc[8];
#pragma unroll
    for (int k = 0; k < 8; k++) acc[k] = 0.f;
    if (g_notkeep[j]) {
#pragma unroll
        for (int wq = 0; wq < 4; wq++) {
            int w = lane + wq * 32;
            unsigned myw = g_CMT[j * NWm + w];
            unsigned act = __ballot_sync(0xffffffffu, myw != 0u);
            while (act) {
                int src = __ffs(act) - 1; act &= act - 1;
                unsigned word = __shfl_sync(0xffffffffu, myw, src);
                int wg = src + wq * 32;
                while (word) {
                    int b = __ffs(word) - 1; word &= word - 1;
                    int i2 = wg * 32 + b;
                    float fit = B[(size_t)i2 * NN + j];       // broadcast load
                    const float* er = emb + (size_t)i2 * DD + lane;
#pragma unroll
                    for (int k = 0; k < 8; k++) acc[k] += fit * er[k * 32];
                }
            }
        }
    }
    const float* ej = emb + (size_t)j * DD + lane;
#pragma unroll
    for (int k = 0; k < 8; k++)
        outP[(size_t)j * DD + lane + k * 32] = ej[k * 32] + acc[k];
}

// new_w = S^T EMw S (exact integer f32 adds); also sets adj = 1.0 at nonzeros
__global__ __launch_bounds__(128) void k_neww(float* __restrict__ neww,
                                              float* __restrict__ adj) {
    __shared__ unsigned short nb[NN];
    __shared__ unsigned short al[NN];
    __shared__ unsigned R[NN];
    __shared__ int cnt, acnt;
    int i = blockIdx.x, t = threadIdx.x;
    if (t == 0) { cnt = 0; acnt = 0; }
#pragma unroll
    for (int c = 0; c < 32; c++) R[t * 32 + c] = 0u;
    unsigned erw = g_EB[i * NWm + t];
    if ((i >> 5) == t) erw |= 1u << (i & 31);       // EMw has unit diagonal
    unsigned aw = g_CM[i * NWm + t] & g_bmoff[t];
    if (((i >> 5) == t) && g_keep[i]) aw |= 1u << (i & 31);
    __syncthreads();
    unsigned tmp = erw;
    while (tmp) {
        int b = __ffs(tmp) - 1; tmp &= tmp - 1;
        int pos = atomicAdd(&cnt, 1);
        nb[pos] = (unsigned short)(t * 32 + b);
    }
    tmp = aw;
    while (tmp) {
        int b = __ffs(tmp) - 1; tmp &= tmp - 1;
        int pos = atomicAdd(&acnt, 1);
        al[pos] = (unsigned short)(t * 32 + b);
    }
    __syncthreads();
    int nc = cnt, ac = acnt;
    if (ac == 0) return;
    for (int idx = 0; idx < nc; idx++) {
        int jn = nb[idx];
        unsigned sw = g_CM[jn * NWm + t] & g_bmoff[t];
        if (((jn >> 5) == t) && g_keep[jn]) sw |= 1u << (jn & 31);
        while (sw) {
            int b = __ffs(sw) - 1; sw &= sw - 1;
            R[t * 32 + b]++;
        }
    }
    unsigned nz = 0;
#pragma unroll
    for (int c = 0; c < 32; c++)
        if (R[t * 32 + c]) nz |= 1u << c;
    for (int ai = 0; ai < ac; ai++) {
        int a = al[ai];
        size_t base = (size_t)a * NN + t * 32;
        unsigned m = nz;
        while (m) {
            int c = __ffs(m) - 1; m &= m - 1;
            atomicAdd(&neww[base + c], (float)R[t * 32 + c]);
            adj[base + c] = 1.0f;      // same-value race: benign
        }
    }
}

// restore g_att == 0 invariant (precise un-scatter of edge positions)
__global__ void k_clean(const void* __restrict__ ei) {
    int e = blockIdx.x * blockDim.x + threadIdx.x;
    if (e >= EE) return;
    int s = eidx(ei, e), d = eidx(ei, EE + e);
    g_att[(size_t)s * NN + d] = 0.f;
}

// ---------------- launch ------------------------------------------------------
extern "C" void kernel_launch(void* const* d_in, const int* in_sizes, int n_in,
                              void* d_out, int out_size) {
    const float* emb = (const float*)d_in[0];
    const void*  ei  = d_in[1];                 // int32 or int64; sniffed on device
    const float* W   = (const float*)d_in[4];
    const float* bsc = (const float*)d_in[5];

    float* out       = (float*)d_out;
    float* outPooled = out;                                // [N, D]
    float* outAdj    = outPooled + (size_t)NN * DD;        // [N, N]
    float* outW      = outAdj + (size_t)NN * NN;           // [N, N]
    float* outB      = outW + (size_t)NN * NN;             // [N, N]
    float* outMask   = outB + (size_t)NN * NN;             // [N]

    static cudaStream_t s1, s2;
    static cudaEvent_t evRoot, evZ, evBits, evB, evN, evC;
    static int inited = 0;
    if (!inited) {
        cudaStreamCreateWithFlags(&s1, cudaStreamNonBlocking);
        cudaStreamCreateWithFlags(&s2, cudaStreamNonBlocking);
        cudaEventCreateWithFlags(&evRoot, cudaEventDisableTiming);
        cudaEventCreateWithFlags(&evZ, cudaEventDisableTiming);
        cudaEventCreateWithFlags(&evBits, cudaEventDisableTiming);
        cudaEventCreateWithFlags(&evB, cudaEventDisableTiming);
        cudaEventCreateWithFlags(&evN, cudaEventDisableTiming);
        cudaEventCreateWithFlags(&evC, cudaEventDisableTiming);
        inited = 1;
    }

    // fork: s1 zero-fills outW/outAdj/outB concurrently with the front pipeline
    cudaEventRecord(evRoot, 0);
    cudaStreamWaitEvent(s1, evRoot, 0);
    k_zeroWA<<<16384, 256, 0, s1>>>((float4*)outW, (float4*)outAdj, (float4*)outB);
    cudaEventRecord(evZ, s1);

    // main pipeline (legacy stream): pre + fused persistent mid-section
    k_pre<<<1025, 256>>>(emb, W, (const unsigned*)ei);
    k_mid<<<NBLK, 128>>>(ei, bsc, outMask);
    cudaEventRecord(evBits, 0);

    // s1: neww (needs bits + zeroed W/adj), concurrent with B/pooled
    cudaStreamWaitEvent(s1, evBits, 0);
    k_neww<<<NN, 128, 0, s1>>>(outW, outAdj);
    cudaEventRecord(evN, s1);

    // main: B scatter (needs zeroed outB) then pooled
    cudaStreamWaitEvent(0, evZ, 0);
    k_B<<<NN / 8, 256>>>(outB);
    cudaEventRecord(evB, 0);
    k_pooled<<<NN / 8, 256>>>(outPooled, emb, outB);

    // s2: clean att after k_B's last att read
    cudaStreamWaitEvent(s2, evB, 0);
    k_clean<<<EE / 256, 256, 0, s2>>>(ei);
    cudaEventRecord(evC, s2);

    // join everything back to the main stream
    cudaStreamWaitEvent(0, evN, 0);
    cudaStreamWaitEvent(0, evC, 0);
}

// round 14
// speedup vs baseline: 1.5113x; 1.5113x over previous
#include <cuda_runtime.h>
#include <cstdint>
#include <cstddef>

#define NN 4096
#define NWm 128          // 4096 bits / 32
#define DD 256
#define EE 65536

// ---------------- scratch (device globals; no allocation allowed) -------------
// g_att invariant: all-zero at kernel_launch entry (zeroed at module load;
// k_clean restores the invariant by zeroing exactly the scattered positions).
__device__ __align__(16) float g_att[(size_t)NN * NN];   // structure_M scatter (64MB)
__device__ __align__(16) float g_Z[(size_t)NN * DD];     // normalized embeddings (row-major)
__device__ float    g_p[NN], g_q[NN];           // W projections
__device__ float    g_den[NN];                  // segment sum
__device__ float    g_s[EE];                    // per-edge scratch
__device__ __align__(16) unsigned g_EB[NN * NWm];        // raw edge bitmap
__device__ __align__(16) unsigned g_A1[NN * NWm], g_A2[NN * NWm];
__device__ __align__(16) unsigned g_CM[NN * NWm], g_CMT[NN * NWm];
__device__ float    g_num1[NN], g_deg1[NN], g_scores[NN];
__device__ int      g_mask[NN], g_notkeep[NN], g_keep[NN];
__device__ unsigned g_bmoff[NWm];               // (notkeep && keepcol) column bits
__device__ int      g_is64;                     // edge_index dtype flag

__device__ __forceinline__ int eidx(const void* ei, int pos) {
    if (g_is64) return (int)((const long long*)ei)[pos];
    return ((const int*)ei)[pos];
}

// warp-collective dot: z[] holds lane's 8 strided dims of row i; j indexes g_Z.
__device__ __forceinline__ float wdot(const float z[8], int j, int lane) {
    const float* zj = g_Z + (size_t)j * DD + lane;
    float d = 0.f;
#pragma unroll
    for (int k = 0; k < 8; k++) d += z[k] * zj[k * 32];
#pragma unroll
    for (int o = 16; o; o >>= 1) d += __shfl_xor_sync(0xffffffffu, d, o);
    return d;
}

// ---------------- kernels ----------------------------------------------------

// zero outW, outAdj, outB (192 MB) — no deps; runs on a forked stream
__global__ __launch_bounds__(256) void k_zeroWA(float4* __restrict__ outW,
                                                float4* __restrict__ outAdj,
                                                float4* __restrict__ outB) {
    size_t idx = (size_t)blockIdx.x * blockDim.x + threadIdx.x;   // 4Mi float4
    float4 zv = make_float4(0.f, 0.f, 0.f, 0.f);
    outW[idx] = zv;
    outAdj[idx] = zv;
    outB[idx] = zv;
}

// fused: [0,512) zero bitmaps/scratch, [512,1024) norm+proj, 1024 dtype sniff
__global__ __launch_bounds__(256) void k_pre(const float* __restrict__ emb,
                                             const float* __restrict__ W,
                                             const unsigned* __restrict__ ei_raw) {
    int bx = blockIdx.x;
    if (bx < 512) {
        int idx = bx * 256 + threadIdx.x;          // 0..131071 (NN*NWm/4)
        uint4 zu = make_uint4(0u, 0u, 0u, 0u);
        reinterpret_cast<uint4*>(g_EB)[idx] = zu;
        reinterpret_cast<uint4*>(g_CMT)[idx] = zu;
        if (idx < NN) g_den[idx] = 0.f;
        if (idx < NWm) g_bmoff[idx] = 0u;
        return;
    }
    if (bx == 1024) {
        if (threadIdx.x >= 32) return;
        int lane = threadIdx.x;
        int nz = 0;
        for (int k = lane; k < 512; k += 32)
            if (ei_raw[2 * k + 1] != 0u) nz++;
#pragma unroll
        for (int o = 16; o; o >>= 1) nz += __shfl_xor_sync(0xffffffffu, nz, o);
        if (lane == 0) g_is64 = (nz == 0) ? 1 : 0;
        return;
    }
    int warp = (bx - 512) * 8 + (threadIdx.x >> 5);
    int lane = threadIdx.x & 31;
    const float* er = emb + (size_t)warp * DD;
    float v[8], ss = 0.f, p = 0.f, q = 0.f;
#pragma unroll
    for (int k = 0; k < 8; k++) {
        int d = lane + k * 32;
        float x = er[d];
        v[k] = x; ss += x * x; p += x * W[d]; q += x * W[DD + d];
    }
#pragma unroll
    for (int o = 16; o; o >>= 1) {
        ss += __shfl_xor_sync(0xffffffffu, ss, o);
        p  += __shfl_xor_sync(0xffffffffu, p, o);
        q  += __shfl_xor_sync(0xffffffffu, q, o);
    }
    float inv = 1.0f / fmaxf(sqrtf(ss), 1e-12f);
    float* zr = g_Z + (size_t)warp * DD;
#pragma unroll
    for (int k = 0; k < 8; k++) zr[lane + k * 32] = v[k] * inv;
    if (lane == 0) { g_p[warp] = p; g_q[warp] = q; }
}

// edges: score, exp (no max shift — ratio-invariant), segment sum, edge bitmap
__global__ void k_edge12(const void* __restrict__ ei, const float* __restrict__ bsc) {
    int e = blockIdx.x * blockDim.x + threadIdx.x;
    if (e >= EE) return;
    int s = eidx(ei, e), d = eidx(ei, EE + e);
    float x = g_p[s] + g_q[d] + bsc[0];
    x = (x >= 0.f) ? x : 0.01f * x;
    float ex = expf(x);
    g_s[e] = ex;
    atomicAdd(&g_den[s], ex);
    atomicOr(&g_EB[s * NWm + (d >> 5)], 1u << (d & 31));
}
__global__ void k_edge3(const void* __restrict__ ei) {
    int e = blockIdx.x * blockDim.x + threadIdx.x;
    if (e >= EE) return;
    int s = eidx(ei, e), d = eidx(ei, EE + e);
    float att = g_s[e] / g_den[s];
    atomicAdd(&g_att[(size_t)s * NN + d], att);
}

// A1 = edges (offdiag) passing fitness threshold; num1/deg1 per row.
__global__ void k_A1() {
    int i = (blockIdx.x * blockDim.x + threadIdx.x) >> 5;
    int lane = threadIdx.x & 31;
    if (i >= NN) return;
    float z[8];
    const float* zi = g_Z + (size_t)i * DD;
#pragma unroll
    for (int k = 0; k < 8; k++) z[k] = zi[lane + 32 * k];
    float num = 0.f;
    int deg = 0;
#pragma unroll
    for (int wq = 0; wq < 4; wq++) {
        int w = lane + wq * 32;
        unsigned myw = g_EB[i * NWm + w];
        if ((i >> 5) == w) myw &= ~(1u << (i & 31));   // offdiag
        unsigned outw = 0u;
        unsigned act = __ballot_sync(0xffffffffu, myw != 0u);
        while (act) {
            int src = __ffs(act) - 1; act &= act - 1;
            unsigned word = __shfl_sync(0xffffffffu, myw, src);
            int wg = src + wq * 32;
            unsigned ob = 0u;
            while (word) {
                int b = __ffs(word) - 1; word &= word - 1;
                int j = wg * 32 + b;
                float fit = wdot(z, j, lane) + g_att[(size_t)i * NN + j];
                if (fit >= 0.1f) { ob |= 1u << b; num += fit; deg++; }
            }
            if (lane == src) outw = ob;
        }
        g_A1[i * NWm + w] = outw;
    }
    if (lane == 0) { g_num1[i] = num; g_deg1[i] = (float)deg; }
}

// A2 = (A1@A1>0)&offdiag&~A1 ; CM ; CMT scatter ; fused num2/deg2 + final scores
__global__ __launch_bounds__(128) void k_A2() {
    __shared__ unsigned short nb[NN];
    __shared__ float zi_s[DD];
    __shared__ float rnum[128];
    __shared__ int rdeg[128];
    __shared__ int cnt;
    int i = blockIdx.x, t = threadIdx.x;
    if (t == 0) cnt = 0;
    unsigned rw = g_A1[i * NWm + t];
    for (int k = t; k < DD; k += 128) zi_s[k] = g_Z[(size_t)i * DD + k];
    __syncthreads();
    unsigned tmp = rw;
    while (tmp) {
        int b = __ffs(tmp) - 1; tmp &= tmp - 1;
        int pos = atomicAdd(&cnt, 1);
        nb[pos] = (unsigned short)(t * 32 + b);
    }
    __syncthreads();
    unsigned acc = 0;
    int nc = cnt;
    for (int idx = 0; idx < nc; idx++) acc |= g_A1[(int)nb[idx] * NWm + t];
    unsigned diagm = ((i >> 5) == t) ? (1u << (i & 31)) : 0u;
    unsigned a2 = acc & ~rw & ~diagm;
    g_A2[i * NWm + t] = a2;
    unsigned cm = rw | a2;
    g_CM[i * NWm + t] = cm;
    unsigned word = cm;
    unsigned ibit = 1u << (i & 31);
    int iw = i >> 5;
    while (word) {
        int b = __ffs(word) - 1; word &= word - 1;
        int j = t * 32 + b;
        atomicOr(&g_CMT[j * NWm + iw], ibit);
    }
    // fused num2/deg2 over this thread's a2 word (serial dots vs smem Z_i)
    float num = 0.f;
    int deg = 0;
    unsigned w2 = a2;
    while (w2) {
        int b = __ffs(w2) - 1; w2 &= w2 - 1;
        int j = t * 32 + b;
        const float4* zj = reinterpret_cast<const float4*>(g_Z + (size_t)j * DD);
        float d = 0.f;
#pragma unroll 16
        for (int k = 0; k < 64; k++) {
            float4 v = zj[k];
            d += zi_s[4 * k] * v.x + zi_s[4 * k + 1] * v.y
               + zi_s[4 * k + 2] * v.z + zi_s[4 * k + 3] * v.w;
        }
        num += d + g_att[(size_t)i * NN + j];
        deg++;
    }
    rnum[t] = num; rdeg[t] = deg;
    __syncthreads();
    for (int o = 64; o; o >>= 1) {
        if (t < o) { rnum[t] += rnum[t + o]; rdeg[t] += rdeg[t + o]; }
        __syncthreads();
    }
    if (t == 0) {
        float d1 = g_deg1[i];
        float s1 = (d1 > 0.f) ? g_num1[i] / d1 : 0.f;
        float s2 = (rdeg[0] > 0) ? rnum[0] / (float)rdeg[0] : 0.f;
        g_scores[i] = 0.5f * (s1 + s2);
    }
}

__global__ void k_mask(float* __restrict__ outMask) {
    int i = (blockIdx.x * blockDim.x + threadIdx.x) >> 5;
    int lane = threadIdx.x & 31;
    if (i >= NN) return;
    float si = g_scores[i];
    bool ok = si > 0.f;
#pragma unroll
    for (int wq = 0; wq < 4; wq++) {
        int w = lane + wq * 32;
        unsigned word = g_A1[i * NWm + w];
        while (word) {
            int b = __ffs(word) - 1; word &= word - 1;
            if (!(si > g_scores[w * 32 + b])) { ok = false; word = 0; }
        }
    }
    ok = __all_sync(0xffffffffu, ok);
    if (lane == 0) { g_mask[i] = ok ? 1 : 0; outMask[i] = ok ? 1.f : 0.f; }
}

// flags + bmoff bits fused (atomicOr; g_bmoff zeroed in k_pre)
__global__ void k_flags() {
    int i = (blockIdx.x * blockDim.x + threadIdx.x) >> 5;
    int lane = threadIdx.x & 31;
    if (i >= NN) return;
    bool red = false;
    int colc = 0;
#pragma unroll
    for (int wq = 0; wq < 4; wq++) {
        int w = lane + wq * 32;
        unsigned cmw = g_CM[i * NWm + w];
        while (cmw) {
            int b = __ffs(cmw) - 1; cmw &= cmw - 1;
            if (g_mask[w * 32 + b]) { red = true; cmw = 0; }
        }
        colc += __popc(g_CMT[i * NWm + w]);
    }
    red = __any_sync(0xffffffffu, red);
#pragma unroll
    for (int o = 16; o; o >>= 1) colc += __shfl_xor_sync(0xffffffffu, colc, o);
    if (lane == 0) {
        bool reduced = red || (colc == 0);
        bool keeping = (!g_mask[i]) && (!reduced);
        g_notkeep[i] = keeping ? 0 : 1;
        g_keep[i]    = reduced ? 0 : 1;
        if (!keeping && !reduced)                      // notkeep && keepcol
            atomicOr(&g_bmoff[i >> 5], 1u << (i & 31));
    }
}

// B = S_w sparse scatter (outB pre-zeroed on forked stream); warp per row
__global__ void k_B(float* __restrict__ outB) {
    int i = (blockIdx.x * blockDim.x + threadIdx.x) >> 5;
    int lane = threadIdx.x & 31;
    if (i >= NN) return;
    float z[8];
    const float* zi = g_Z + (size_t)i * DD;
#pragma unroll
    for (int k = 0; k < 8; k++) z[k] = zi[lane + 32 * k];
#pragma unroll
    for (int wq = 0; wq < 4; wq++) {
        int w = lane + wq * 32;
        unsigned myw = g_CM[i * NWm + w] & g_bmoff[w];
        unsigned act = __ballot_sync(0xffffffffu, myw != 0u);
        while (act) {
            int src = __ffs(act) - 1; act &= act - 1;
            unsigned word = __shfl_sync(0xffffffffu, myw, src);
            int wg = src + wq * 32;
            while (word) {
                int b = __ffs(word) - 1; word &= word - 1;
                int j = wg * 32 + b;
                float fit = wdot(z, j, lane) + g_att[(size_t)i * NN + j];
                if (lane == 0) outB[(size_t)i * NN + j] = fit;
            }
        }
    }
    if (lane == 0) outB[(size_t)i * NN + i] = g_keep[i] ? 1.f : 0.f;
}

// pooled = S_w^T @ emb via CM^T; recomputes fitness (same arithmetic as k_B),
// so it has NO dependence on outB and runs concurrently with it.
__global__ void k_pooled(float* __restrict__ outP, const float* __restrict__ emb) {
    int j = (blockIdx.x * blockDim.x + threadIdx.x) >> 5;
    int lane = threadIdx.x & 31;
    if (j >= NN) return;
    if (!g_keep[j]) {
#pragma unroll
        for (int k = 0; k < 8; k++) outP[(size_t)j * DD + lane + k * 32] = 0.f;
        return;
    }
    float acc[8];
#pragma unroll
    for (int k = 0; k < 8; k++) acc[k] = 0.f;
    if (g_notkeep[j]) {
        float zj[8];
        const float* zr = g_Z + (size_t)j * DD;
#pragma unroll
        for (int k = 0; k < 8; k++) zj[k] = zr[lane + 32 * k];
#pragma unroll
        for (int wq = 0; wq < 4; wq++) {
            int w = lane + wq * 32;
            unsigned myw = g_CMT[j * NWm + w];
            unsigned act = __ballot_sync(0xffffffffu, myw != 0u);
            while (act) {
                int src = __ffs(act) - 1; act &= act - 1;
                unsigned word = __shfl_sync(0xffffffffu, myw, src);
                int wg = src + wq * 32;
                while (word) {
                    int b = __ffs(word) - 1; word &= word - 1;
                    int i2 = wg * 32 + b;
                    float fit = wdot(zj, i2, lane) + g_att[(size_t)i2 * NN + j];
                    const float* er = emb + (size_t)i2 * DD + lane;
#pragma unroll
                    for (int k = 0; k < 8; k++) acc[k] += fit * er[k * 32];
                }
            }
        }
    }
    const float* ej = emb + (size_t)j * DD + lane;
#pragma unroll
    for (int k = 0; k < 8; k++)
        outP[(size_t)j * DD + lane + k * 32] = ej[k * 32] + acc[k];
}

// new_w = S^T EMw S (exact integer f32 adds); also sets adj = 1.0 at nonzeros
__global__ __launch_bounds__(128) void k_neww(float* __restrict__ neww,
                                              float* __restrict__ adj) {
    __shared__ unsigned short nb[NN];
    __shared__ unsigned short al[NN];
    __shared__ unsigned R[NN];
    __shared__ int cnt, acnt;
    int i = blockIdx.x, t = threadIdx.x;
    if (t == 0) { cnt = 0; acnt = 0; }
#pragma unroll
    for (int c = 0; c < 32; c++) R[t * 32 + c] = 0u;
    unsigned erw = g_EB[i * NWm + t];
    if ((i >> 5) == t) erw |= 1u << (i & 31);       // EMw has unit diagonal
    unsigned aw = g_CM[i * NWm + t] & g_bmoff[t];
    if (((i >> 5) == t) && g_keep[i]) aw |= 1u << (i & 31);
    __syncthreads();
    unsigned tmp = erw;
    while (tmp) {
        int b = __ffs(tmp) - 1; tmp &= tmp - 1;
        int pos = atomicAdd(&cnt, 1);
        nb[pos] = (unsigned short)(t * 32 + b);
    }
    tmp = aw;
    while (tmp) {
        int b = __ffs(tmp) - 1; tmp &= tmp - 1;
        int pos = atomicAdd(&acnt, 1);
        al[pos] = (unsigned short)(t * 32 + b);
    }
    __syncthreads();
    int nc = cnt, ac = acnt;
    if (ac == 0) return;
    for (int idx = 0; idx < nc; idx++) {
        int jn = nb[idx];
        unsigned sw = g_CM[jn * NWm + t] & g_bmoff[t];
        if (((jn >> 5) == t) && g_keep[jn]) sw |= 1u << (jn & 31);
        while (sw) {
            int b = __ffs(sw) - 1; sw &= sw - 1;
            R[t * 32 + b]++;
        }
    }
    unsigned nz = 0;
#pragma unroll
    for (int c = 0; c < 32; c++)
        if (R[t * 32 + c]) nz |= 1u << c;
    for (int ai = 0; ai < ac; ai++) {
        int a = al[ai];
        size_t base = (size_t)a * NN + t * 32;
        unsigned m = nz;
        while (m) {
            int c = __ffs(m) - 1; m &= m - 1;
            atomicAdd(&neww[base + c], (float)R[t * 32 + c]);
            adj[base + c] = 1.0f;      // same-value race: benign
        }
    }
}

// restore g_att == 0 invariant (precise un-scatter of edge positions)
__global__ void k_clean(const void* __restrict__ ei) {
    int e = blockIdx.x * blockDim.x + threadIdx.x;
    if (e >= EE) return;
    int s = eidx(ei, e), d = eidx(ei, EE + e);
    g_att[(size_t)s * NN + d] = 0.f;
}

// ---------------- launch ------------------------------------------------------
extern "C" void kernel_launch(void* const* d_in, const int* in_sizes, int n_in,
                              void* d_out, int out_size) {
    const float* emb = (const float*)d_in[0];
    const void*  ei  = d_in[1];                 // int32 or int64; sniffed on device
    const float* W   = (const float*)d_in[4];
    const float* bsc = (const float*)d_in[5];

    float* out       = (float*)d_out;
    float* outPooled = out;                                // [N, D]
    float* outAdj    = outPooled + (size_t)NN * DD;        // [N, N]
    float* outW      = outAdj + (size_t)NN * NN;           // [N, N]
    float* outB      = outW + (size_t)NN * NN;             // [N, N]
    float* outMask   = outB + (size_t)NN * NN;             // [N]

    static cudaStream_t s1, s2;
    static cudaEvent_t evRoot, evZ, evF, evB, evN, evC;
    static int inited = 0;
    if (!inited) {
        cudaStreamCreateWithFlags(&s1, cudaStreamNonBlocking);
        cudaStreamCreateWithFlags(&s2, cudaStreamNonBlocking);
        cudaEventCreateWithFlags(&evRoot, cudaEventDisableTiming);
        cudaEventCreateWithFlags(&evZ, cudaEventDisableTiming);
        cudaEventCreateWithFlags(&evF, cudaEventDisableTiming);
        cudaEventCreateWithFlags(&evB, cudaEventDisableTiming);
        cudaEventCreateWithFlags(&evN, cudaEventDisableTiming);
        cudaEventCreateWithFlags(&evC, cudaEventDisableTiming);
        inited = 1;
    }

    // fork: s1 zero-fills outW/outAdj/outB concurrently with the front pipeline
    cudaEventRecord(evRoot, 0);
    cudaStreamWaitEvent(s1, evRoot, 0);
    k_zeroWA<<<16384, 256, 0, s1>>>((float4*)outW, (float4*)outAdj, (float4*)outB);
    cudaEventRecord(evZ, s1);

    // main pipeline (legacy stream)
    k_pre<<<1025, 256>>>(emb, W, (const unsigned*)ei);
    k_edge12<<<EE / 256, 256>>>(ei, bsc);
    k_edge3<<<EE / 256, 256>>>(ei);
    k_A1<<<NN / 8, 256>>>();
    k_A2<<<NN, 128>>>();
    k_mask<<<NN / 8, 256>>>(outMask);
    k_flags<<<NN / 8, 256>>>();
    cudaEventRecord(evF, 0);

    // s1: neww (needs flags/bmoff + zeroed W/adj), concurrent with B/pooled
    cudaStreamWaitEvent(s1, evF, 0);
    k_neww<<<NN, 128, 0, s1>>>(outW, outAdj);
    cudaEventRecord(evN, s1);

    // s2: pooled (fitness recompute; independent of outB), concurrent with B
    cudaStreamWaitEvent(s2, evF, 0);
    k_pooled<<<NN / 8, 256, 0, s2>>>(outPooled, emb);

    // main: B scatter (needs zeroed outB)
    cudaStreamWaitEvent(0, evZ, 0);
    k_B<<<NN / 8, 256>>>(outB);
    cudaEventRecord(evB, 0);

    // s2 (in-order after pooled): clean att once B's reads are also done
    cudaStreamWaitEvent(s2, evB, 0);
    k_clean<<<EE / 256, 256, 0, s2>>>(ei);
    cudaEventRecord(evC, s2);

    // join everything back to the main stream
    cudaStreamWaitEvent(0, evN, 0);
    cudaStreamWaitEvent(0, evC, 0);
}

// round 15
// speedup vs baseline: 1.6833x; 1.1138x over previous
#include <cuda_runtime.h>
#include <cstdint>
#include <cstddef>

#define NN 4096
#define NWm 128          // 4096 bits / 32
#define DD 256
#define EE 65536

// ---------------- scratch (device globals; no allocation allowed) -------------
// g_att invariant: all-zero at kernel_launch entry (zeroed at module load;
// k_clean restores the invariant by zeroing exactly the scattered positions).
__device__ __align__(16) float g_att[(size_t)NN * NN];   // structure_M scatter (64MB)
__device__ __align__(16) float g_Z[(size_t)NN * DD];     // normalized embeddings (row-major)
__device__ float    g_p[NN], g_q[NN];           // W projections
__device__ float    g_den[NN];                  // segment sum
__device__ float    g_s[EE];                    // per-edge scratch
__device__ __align__(16) unsigned g_EB[NN * NWm];        // raw edge bitmap
__device__ __align__(16) unsigned g_A1[NN * NWm], g_A2[NN * NWm];
__device__ __align__(16) unsigned g_CM[NN * NWm], g_CMT[NN * NWm];
__device__ float    g_num1[NN], g_deg1[NN], g_scores[NN];
__device__ int      g_mask[NN], g_notkeep[NN], g_keep[NN];
__device__ unsigned g_bmoff[NWm];               // (notkeep && keepcol) column bits
__device__ int      g_is64;                     // edge_index dtype flag

__device__ __forceinline__ int eidx(const void* ei, int pos) {
    if (g_is64) return (int)((const long long*)ei)[pos];
    return ((const int*)ei)[pos];
}

// warp-collective dot: z[] holds lane's 8 strided dims of row i; j indexes g_Z.
__device__ __forceinline__ float wdot(const float z[8], int j, int lane) {
    const float* zj = g_Z + (size_t)j * DD + lane;
    float d = 0.f;
#pragma unroll
    for (int k = 0; k < 8; k++) d += z[k] * zj[k * 32];
#pragma unroll
    for (int o = 16; o; o >>= 1) d += __shfl_xor_sync(0xffffffffu, d, o);
    return d;
}

// ---------------- kernels ----------------------------------------------------

// zero outW, outAdj, outB (192 MB) — no deps; runs on a forked stream
__global__ __launch_bounds__(256) void k_zeroWA(float4* __restrict__ outW,
                                                float4* __restrict__ outAdj,
                                                float4* __restrict__ outB) {
    size_t idx = (size_t)blockIdx.x * blockDim.x + threadIdx.x;   // 4Mi float4
    float4 zv = make_float4(0.f, 0.f, 0.f, 0.f);
    outW[idx] = zv;
    outAdj[idx] = zv;
    outB[idx] = zv;
}

// fused: [0,512) zero bitmaps/scratch, [512,1024) norm+proj, 1024 dtype sniff
__global__ __launch_bounds__(256) void k_pre(const float* __restrict__ emb,
                                             const float* __restrict__ W,
                                             const unsigned* __restrict__ ei_raw) {
    int bx = blockIdx.x;
    if (bx < 512) {
        int idx = bx * 256 + threadIdx.x;          // 0..131071 (NN*NWm/4)
        uint4 zu = make_uint4(0u, 0u, 0u, 0u);
        reinterpret_cast<uint4*>(g_EB)[idx] = zu;
        reinterpret_cast<uint4*>(g_CMT)[idx] = zu;
        reinterpret_cast<uint4*>(g_A1)[idx] = zu;
        if (idx < NN) { g_den[idx] = 0.f; g_num1[idx] = 0.f; g_deg1[idx] = 0.f; }
        if (idx < NWm) g_bmoff[idx] = 0u;
        return;
    }
    if (bx == 1024) {
        if (threadIdx.x >= 32) return;
        int lane = threadIdx.x;
        int nz = 0;
        for (int k = lane; k < 512; k += 32)
            if (ei_raw[2 * k + 1] != 0u) nz++;
#pragma unroll
        for (int o = 16; o; o >>= 1) nz += __shfl_xor_sync(0xffffffffu, nz, o);
        if (lane == 0) g_is64 = (nz == 0) ? 1 : 0;
        return;
    }
    int warp = (bx - 512) * 8 + (threadIdx.x >> 5);
    int lane = threadIdx.x & 31;
    const float* er = emb + (size_t)warp * DD;
    float v[8], ss = 0.f, p = 0.f, q = 0.f;
#pragma unroll
    for (int k = 0; k < 8; k++) {
        int d = lane + k * 32;
        float x = er[d];
        v[k] = x; ss += x * x; p += x * W[d]; q += x * W[DD + d];
    }
#pragma unroll
    for (int o = 16; o; o >>= 1) {
        ss += __shfl_xor_sync(0xffffffffu, ss, o);
        p  += __shfl_xor_sync(0xffffffffu, p, o);
        q  += __shfl_xor_sync(0xffffffffu, q, o);
    }
    float inv = 1.0f / fmaxf(sqrtf(ss), 1e-12f);
    float* zr = g_Z + (size_t)warp * DD;
#pragma unroll
    for (int k = 0; k < 8; k++) zr[lane + k * 32] = v[k] * inv;
    if (lane == 0) { g_p[warp] = p; g_q[warp] = q; }
}

// edges: score, exp (no max shift — ratio-invariant), segment sum, edge bitmap
__global__ void k_edge12(const void* __restrict__ ei, const float* __restrict__ bsc) {
    int e = blockIdx.x * blockDim.x + threadIdx.x;
    if (e >= EE) return;
    int s = eidx(ei, e), d = eidx(ei, EE + e);
    float x = g_p[s] + g_q[d] + bsc[0];
    x = (x >= 0.f) ? x : 0.01f * x;
    float ex = expf(x);
    g_s[e] = ex;
    atomicAdd(&g_den[s], ex);
    atomicOr(&g_EB[s * NWm + (d >> 5)], 1u << (d & 31));
}
__global__ void k_edge3(const void* __restrict__ ei) {
    int e = blockIdx.x * blockDim.x + threadIdx.x;
    if (e >= EE) return;
    int s = eidx(ei, e), d = eidx(ei, EE + e);
    float att = g_s[e] / g_den[s];
    atomicAdd(&g_att[(size_t)s * NN + d], att);
}

// edge-parallel A1: one thread per edge; exactly-once accumulation via atomicOr
__global__ void k_eA1(const void* __restrict__ ei) {
    int e = blockIdx.x * blockDim.x + threadIdx.x;
    if (e >= EE) return;
    int s = eidx(ei, e), d = eidx(ei, EE + e);
    if (s == d) return;                            // offdiag
    float att = g_att[(size_t)s * NN + d];         // total (all duplicates summed)
    const float4* zs = reinterpret_cast<const float4*>(g_Z + (size_t)s * DD);
    const float4* zd = reinterpret_cast<const float4*>(g_Z + (size_t)d * DD);
    float dot = 0.f;
#pragma unroll 8
    for (int k = 0; k < 64; k++) {
        float4 a = zs[k], b = zd[k];
        dot += a.x * b.x + a.y * b.y + a.z * b.z + a.w * b.w;
    }
    float fit = dot + att;
    if (fit >= 0.1f) {
        unsigned bit = 1u << (d & 31);
        unsigned old = atomicOr(&g_A1[s * NWm + (d >> 5)], bit);
        if (!(old & bit)) {                        // first setter of this position
            atomicAdd(&g_num1[s], fit);
            atomicAdd(&g_deg1[s], 1.f);
        }
    }
}

// A2 = (A1@A1>0)&offdiag&~A1 ; CM ; CMT scatter ; balanced num2 + final scores
__global__ __launch_bounds__(128) void k_A2() {
    __shared__ unsigned short nb[NN];              // A1-neighbor list, then A2 list
    __shared__ float zi_s[DD];
    __shared__ float rnum[4];
    __shared__ int cnt, cnt2;
    int i = blockIdx.x, t = threadIdx.x;
    int lane = t & 31, wl = t >> 5;                // warp 0..3
    if (t == 0) { cnt = 0; cnt2 = 0; }
    if (t < 4) rnum[t] = 0.f;
    unsigned rw = g_A1[i * NWm + t];
    for (int k = t; k < DD; k += 128) zi_s[k] = g_Z[(size_t)i * DD + k];
    __syncthreads();
    unsigned tmp = rw;
    while (tmp) {
        int b = __ffs(tmp) - 1; tmp &= tmp - 1;
        int pos = atomicAdd(&cnt, 1);
        nb[pos] = (unsigned short)(t * 32 + b);
    }
    __syncthreads();
    unsigned acc = 0;
    int nc = cnt;
    for (int idx = 0; idx < nc; idx++) acc |= g_A1[(int)nb[idx] * NWm + t];
    unsigned diagm = ((i >> 5) == t) ? (1u << (i & 31)) : 0u;
    unsigned a2 = acc & ~rw & ~diagm;
    g_A2[i * NWm + t] = a2;
    unsigned cm = rw | a2;
    g_CM[i * NWm + t] = cm;
    unsigned word = cm;
    unsigned ibit = 1u << (i & 31);
    int iw = i >> 5;
    while (word) {
        int b = __ffs(word) - 1; word &= word - 1;
        int j = t * 32 + b;
        atomicOr(&g_CMT[j * NWm + iw], ibit);
    }
    __syncthreads();                               // nb free for reuse as A2 list
    unsigned w2 = a2;
    while (w2) {
        int b = __ffs(w2) - 1; w2 &= w2 - 1;
        int pos = atomicAdd(&cnt2, 1);
        nb[pos] = (unsigned short)(t * 32 + b);
    }
    __syncthreads();
    int n2 = cnt2;
    float num = 0.f;
    for (int idx = wl; idx < n2; idx += 4) {       // warp-collective dots, balanced
        int j = nb[idx];
        const float* zj = g_Z + (size_t)j * DD + lane;
        float d = 0.f;
#pragma unroll
        for (int k = 0; k < 8; k++) d += zi_s[lane + 32 * k] * zj[32 * k];
#pragma unroll
        for (int o = 16; o; o >>= 1) d += __shfl_xor_sync(0xffffffffu, d, o);
        if (lane == 0) num += d + g_att[(size_t)i * NN + j];
    }
    if (lane == 0) rnum[wl] = num;
    __syncthreads();
    if (t == 0) {
        float tot = rnum[0] + rnum[1] + rnum[2] + rnum[3];
        float d1 = g_deg1[i];
        float s1 = (d1 > 0.f) ? g_num1[i] / d1 : 0.f;
        float s2 = (n2 > 0) ? tot / (float)n2 : 0.f;
        g_scores[i] = 0.5f * (s1 + s2);
    }
}

__global__ void k_mask(float* __restrict__ outMask) {
    int i = (blockIdx.x * blockDim.x + threadIdx.x) >> 5;
    int lane = threadIdx.x & 31;
    if (i >= NN) return;
    float si = g_scores[i];
    bool ok = si > 0.f;
#pragma unroll
    for (int wq = 0; wq < 4; wq++) {
        int w = lane + wq * 32;
        unsigned word = g_A1[i * NWm + w];
        while (word) {
            int b = __ffs(word) - 1; word &= word - 1;
            if (!(si > g_scores[w * 32 + b])) { ok = false; word = 0; }
        }
    }
    ok = __all_sync(0xffffffffu, ok);
    if (lane == 0) { g_mask[i] = ok ? 1 : 0; outMask[i] = ok ? 1.f : 0.f; }
}

// flags + bmoff bits fused (atomicOr; g_bmoff zeroed in k_pre)
__global__ void k_flags() {
    int i = (blockIdx.x * blockDim.x + threadIdx.x) >> 5;
    int lane = threadIdx.x & 31;
    if (i >= NN) return;
    bool red = false;
    int colc = 0;
#pragma unroll
    for (int wq = 0; wq < 4; wq++) {
        int w = lane + wq * 32;
        unsigned cmw = g_CM[i * NWm + w];
        while (cmw) {
            int b = __ffs(cmw) - 1; cmw &= cmw - 1;
            if (g_mask[w * 32 + b]) { red = true; cmw = 0; }
        }
        colc += __popc(g_CMT[i * NWm + w]);
    }
    red = __any_sync(0xffffffffu, red);
#pragma unroll
    for (int o = 16; o; o >>= 1) colc += __shfl_xor_sync(0xffffffffu, colc, o);
    if (lane == 0) {
        bool reduced = red || (colc == 0);
        bool keeping = (!g_mask[i]) && (!reduced);
        g_notkeep[i] = keeping ? 0 : 1;
        g_keep[i]    = reduced ? 0 : 1;
        if (!keeping && !reduced)                      // notkeep && keepcol
            atomicOr(&g_bmoff[i >> 5], 1u << (i & 31));
    }
}

// B = S_w sparse scatter (outB pre-zeroed on forked stream); warp per row
__global__ void k_B(float* __restrict__ outB) {
    int i = (blockIdx.x * blockDim.x + threadIdx.x) >> 5;
    int lane = threadIdx.x & 31;
    if (i >= NN) return;
    float z[8];
    const float* zi = g_Z + (size_t)i * DD;
#pragma unroll
    for (int k = 0; k < 8; k++) z[k] = zi[lane + 32 * k];
#pragma unroll
    for (int wq = 0; wq < 4; wq++) {
        int w = lane + wq * 32;
        unsigned myw = g_CM[i * NWm + w] & g_bmoff[w];
        unsigned act = __ballot_sync(0xffffffffu, myw != 0u);
        while (act) {
            int src = __ffs(act) - 1; act &= act - 1;
            unsigned word = __shfl_sync(0xffffffffu, myw, src);
            int wg = src + wq * 32;
            while (word) {
                int b = __ffs(word) - 1; word &= word - 1;
                int j = wg * 32 + b;
                float fit = wdot(z, j, lane) + g_att[(size_t)i * NN + j];
                if (lane == 0) outB[(size_t)i * NN + j] = fit;
            }
        }
    }
    if (lane == 0) outB[(size_t)i * NN + i] = g_keep[i] ? 1.f : 0.f;
}

// pooled = S_w^T @ emb via CM^T; recomputes fitness (same arithmetic as k_B),
// so it has NO dependence on outB and runs concurrently with it.
__global__ void k_pooled(float* __restrict__ outP, const float* __restrict__ emb) {
    int j = (blockIdx.x * blockDim.x + threadIdx.x) >> 5;
    int lane = threadIdx.x & 31;
    if (j >= NN) return;
    if (!g_keep[j]) {
#pragma unroll
        for (int k = 0; k < 8; k++) outP[(size_t)j * DD + lane + k * 32] = 0.f;
        return;
    }
    float acc[8];
#pragma unroll
    for (int k = 0; k < 8; k++) acc[k] = 0.f;
    if (g_notkeep[j]) {
        float zj[8];
        const float* zr = g_Z + (size_t)j * DD;
#pragma unroll
        for (int k = 0; k < 8; k++) zj[k] = zr[lane + 32 * k];
#pragma unroll
        for (int wq = 0; wq < 4; wq++) {
            int w = lane + wq * 32;
            unsigned myw = g_CMT[j * NWm + w];
            unsigned act = __ballot_sync(0xffffffffu, myw != 0u);
            while (act) {
                int src = __ffs(act) - 1; act &= act - 1;
                unsigned word = __shfl_sync(0xffffffffu, myw, src);
                int wg = src + wq * 32;
                while (word) {
                    int b = __ffs(word) - 1; word &= word - 1;
                    int i2 = wg * 32 + b;
                    float fit = wdot(zj, i2, lane) + g_att[(size_t)i2 * NN + j];
                    const float* er = emb + (size_t)i2 * DD + lane;
#pragma unroll
                    for (int k = 0; k < 8; k++) acc[k] += fit * er[k * 32];
                }
            }
        }
    }
    const float* ej = emb + (size_t)j * DD + lane;
#pragma unroll
    for (int k = 0; k < 8; k++)
        outP[(size_t)j * DD + lane + k * 32] = ej[k * 32] + acc[k];
}

// new_w = S^T EMw S (exact integer f32 adds); adj = 1.0 at nonzeros.
// 256 threads: thread owns half a word (16 R columns) -> 2x parallel vs 128.
__global__ __launch_bounds__(256) void k_neww(float* __restrict__ neww,
                                              float* __restrict__ adj) {
    __shared__ unsigned short nb[NN];
    __shared__ unsigned short al[NN];
    __shared__ unsigned R[NN];
    __shared__ int cnt, acnt;
    int i = blockIdx.x, t = threadIdx.x;
    int w2 = t >> 1, half = t & 1;                 // word, half-word
    if (t == 0) { cnt = 0; acnt = 0; }
#pragma unroll
    for (int c = 0; c < 16; c++) R[w2 * 32 + half * 16 + c] = 0u;
    unsigned erw = 0u, aw = 0u;
    if (t < 128) {
        erw = g_EB[i * NWm + t];
        if ((i >> 5) == t) erw |= 1u << (i & 31);  // EMw has unit diagonal
        aw = g_CM[i * NWm + t] & g_bmoff[t];
        if (((i >> 5) == t) && g_keep[i]) aw |= 1u << (i & 31);
    }
    __syncthreads();
    if (t < 128) {
        unsigned tmp = erw;
        while (tmp) {
            int b = __ffs(tmp) - 1; tmp &= tmp - 1;
            int pos = atomicAdd(&cnt, 1);
            nb[pos] = (unsigned short)(t * 32 + b);
        }
        tmp = aw;
        while (tmp) {
            int b = __ffs(tmp) - 1; tmp &= tmp - 1;
            int pos = atomicAdd(&acnt, 1);
            al[pos] = (unsigned short)(t * 32 + b);
        }
    }
    __syncthreads();
    int nc = cnt, ac = acnt;
    if (ac == 0) return;
    unsigned hmask = 0xFFFFu << (half * 16);
    for (int idx = 0; idx < nc; idx++) {
        int jn = nb[idx];
        unsigned sw = g_CM[jn * NWm + w2] & g_bmoff[w2] & hmask;
        if (((jn >> 5) == w2) && g_keep[jn]) sw |= (1u << (jn & 31)) & hmask;
        while (sw) {
            int b = __ffs(sw) - 1; sw &= sw - 1;
            R[w2 * 32 + b]++;
        }
    }
    unsigned nz = 0;
#pragma unroll
    for (int c = 0; c < 16; c++)
        if (R[w2 * 32 + half * 16 + c]) nz |= 1u << (half * 16 + c);
    for (int ai = 0; ai < ac; ai++) {
        int a = al[ai];
        size_t base = (size_t)a * NN + w2 * 32;
        unsigned m = nz;
        while (m) {
            int c = __ffs(m) - 1; m &= m - 1;
            atomicAdd(&neww[base + c], (float)R[w2 * 32 + c]);
            adj[base + c] = 1.0f;      // same-value race: benign
        }
    }
}

// restore g_att == 0 invariant (precise un-scatter of edge positions)
__global__ void k_clean(const void* __restrict__ ei) {
    int e = blockIdx.x * blockDim.x + threadIdx.x;
    if (e >= EE) return;
    int s = eidx(ei, e), d = eidx(ei, EE + e);
    g_att[(size_t)s * NN + d] = 0.f;
}

// ---------------- launch ------------------------------------------------------
extern "C" void kernel_launch(void* const* d_in, const int* in_sizes, int n_in,
                              void* d_out, int out_size) {
    const float* emb = (const float*)d_in[0];
    const void*  ei  = d_in[1];                 // int32 or int64; sniffed on device
    const float* W   = (const float*)d_in[4];
    const float* bsc = (const float*)d_in[5];

    float* out       = (float*)d_out;
    float* outPooled = out;                                // [N, D]
    float* outAdj    = outPooled + (size_t)NN * DD;        // [N, N]
    float* outW      = outAdj + (size_t)NN * NN;           // [N, N]
    float* outB      = outW + (size_t)NN * NN;             // [N, N]
    float* outMask   = outB + (size_t)NN * NN;             // [N]

    static cudaStream_t s1, s2;
    static cudaEvent_t evRoot, evZ, evF, evB, evN, evC;
    static int inited = 0;
    if (!inited) {
        cudaStreamCreateWithFlags(&s1, cudaStreamNonBlocking);
        cudaStreamCreateWithFlags(&s2, cudaStreamNonBlocking);
        cudaEventCreateWithFlags(&evRoot, cudaEventDisableTiming);
        cudaEventCreateWithFlags(&evZ, cudaEventDisableTiming);
        cudaEventCreateWithFlags(&evF, cudaEventDisableTiming);
        cudaEventCreateWithFlags(&evB, cudaEventDisableTiming);
        cudaEventCreateWithFlags(&evN, cudaEventDisableTiming);
        cudaEventCreateWithFlags(&evC, cudaEventDisableTiming);
        inited = 1;
    }

    // fork: s1 zero-fills outW/outAdj/outB concurrently with the front pipeline
    cudaEventRecord(evRoot, 0);
    cudaStreamWaitEvent(s1, evRoot, 0);
    k_zeroWA<<<16384, 256, 0, s1>>>((float4*)outW, (float4*)outAdj, (float4*)outB);
    cudaEventRecord(evZ, s1);

    // main pipeline (legacy stream)
    k_pre<<<1025, 256>>>(emb, W, (const unsigned*)ei);
    k_edge12<<<EE / 256, 256>>>(ei, bsc);
    k_edge3<<<EE / 256, 256>>>(ei);
    k_eA1<<<EE / 256, 256>>>(ei);
    k_A2<<<NN, 128>>>();
    k_mask<<<NN / 8, 256>>>(outMask);
    k_flags<<<NN / 8, 256>>>();
    cudaEventRecord(evF, 0);

    // s1: neww (needs flags/bmoff + zeroed W/adj), concurrent with B/pooled
    cudaStreamWaitEvent(s1, evF, 0);
    k_neww<<<NN, 256, 0, s1>>>(outW, outAdj);
    cudaEventRecord(evN, s1);

    // s2: pooled (fitness recompute; independent of outB), concurrent with B
    cudaStreamWaitEvent(s2, evF, 0);
    k_pooled<<<NN / 8, 256, 0, s2>>>(outPooled, emb);

    // main: B scatter (needs zeroed outB)
    cudaStreamWaitEvent(0, evZ, 0);
    k_B<<<NN / 8, 256>>>(outB);
    cudaEventRecord(evB, 0);

    // s2 (in-order after pooled): clean att once B's reads are also done
    cudaStreamWaitEvent(s2, evB, 0);
    k_clean<<<EE / 256, 256, 0, s2>>>(ei);
    cudaEventRecord(evC, s2);

    // join everything back to the main stream
    cudaStreamWaitEvent(0, evN, 0);
    cudaStreamWaitEvent(0, evC, 0);
}

// round 16
// speedup vs baseline: 1.7417x; 1.0347x over previous
#include <cuda_runtime.h>
#include <cstdint>
#include <cstddef>

#define NN 4096
#define NWm 128          // 4096 bits / 32
#define DD 256
#define EE 65536

// ---------------- scratch (device globals; no allocation allowed) -------------
// g_att invariant: all-zero at kernel_launch entry (zeroed at module load;
// k_clean restores the invariant by zeroing exactly the scattered positions).
__device__ __align__(16) float g_att[(size_t)NN * NN];   // structure_M scatter (64MB)
__device__ __align__(16) float g_Z[(size_t)NN * DD];     // normalized embeddings (row-major)
__device__ float    g_p[NN], g_q[NN];           // W projections
__device__ float    g_den[NN];                  // segment sum
__device__ float    g_s[EE];                    // per-edge scratch
__device__ __align__(16) unsigned g_EB[NN * NWm];        // raw edge bitmap
__device__ __align__(16) unsigned g_A1[NN * NWm], g_A2[NN * NWm];
__device__ __align__(16) unsigned g_CM[NN * NWm], g_CMT[NN * NWm];
__device__ float    g_num1[NN], g_deg1[NN], g_scores[NN];
__device__ int      g_mask[NN], g_notkeep[NN], g_keep[NN];
__device__ unsigned g_bmoff[NWm];               // (notkeep && keepcol) column bits
__device__ int      g_is64;                     // edge_index dtype flag

__device__ __forceinline__ int eidx(const void* ei, int pos) {
    if (g_is64) return (int)((const long long*)ei)[pos];
    return ((const int*)ei)[pos];
}

// warp-collective dot: z[] holds lane's 8 strided dims of row i; j indexes g_Z.
__device__ __forceinline__ float wdot(const float z[8], int j, int lane) {
    const float* zj = g_Z + (size_t)j * DD + lane;
    float d = 0.f;
#pragma unroll
    for (int k = 0; k < 8; k++) d += z[k] * zj[k * 32];
#pragma unroll
    for (int o = 16; o; o >>= 1) d += __shfl_xor_sync(0xffffffffu, d, o);
    return d;
}

// ---------------- kernels ----------------------------------------------------

// zero outW, outAdj, outB (192 MB) — no deps; runs on a forked stream
__global__ __launch_bounds__(256) void k_zeroWA(float4* __restrict__ outW,
                                                float4* __restrict__ outAdj,
                                                float4* __restrict__ outB) {
    size_t idx = (size_t)blockIdx.x * blockDim.x + threadIdx.x;   // 4Mi float4
    float4 zv = make_float4(0.f, 0.f, 0.f, 0.f);
    outW[idx] = zv;
    outAdj[idx] = zv;
    outB[idx] = zv;
}

// fused: [0,512) zero bitmaps/scratch, [512,1024) norm+proj, 1024 dtype sniff
__global__ __launch_bounds__(256) void k_pre(const float* __restrict__ emb,
                                             const float* __restrict__ W,
                                             const unsigned* __restrict__ ei_raw) {
    int bx = blockIdx.x;
    if (bx < 512) {
        int idx = bx * 256 + threadIdx.x;          // 0..131071 (NN*NWm/4)
        uint4 zu = make_uint4(0u, 0u, 0u, 0u);
        reinterpret_cast<uint4*>(g_EB)[idx] = zu;
        reinterpret_cast<uint4*>(g_CMT)[idx] = zu;
        reinterpret_cast<uint4*>(g_A1)[idx] = zu;
        if (idx < NN) { g_den[idx] = 0.f; g_num1[idx] = 0.f; g_deg1[idx] = 0.f; }
        if (idx < NWm) g_bmoff[idx] = 0u;
        return;
    }
    if (bx == 1024) {
        if (threadIdx.x >= 32) return;
        int lane = threadIdx.x;
        int nz = 0;
        for (int k = lane; k < 512; k += 32)
            if (ei_raw[2 * k + 1] != 0u) nz++;
#pragma unroll
        for (int o = 16; o; o >>= 1) nz += __shfl_xor_sync(0xffffffffu, nz, o);
        if (lane == 0) g_is64 = (nz == 0) ? 1 : 0;
        return;
    }
    int warp = (bx - 512) * 8 + (threadIdx.x >> 5);
    int lane = threadIdx.x & 31;
    const float* er = emb + (size_t)warp * DD;
    float v[8], ss = 0.f, p = 0.f, q = 0.f;
#pragma unroll
    for (int k = 0; k < 8; k++) {
        int d = lane + k * 32;
        float x = er[d];
        v[k] = x; ss += x * x; p += x * W[d]; q += x * W[DD + d];
    }
#pragma unroll
    for (int o = 16; o; o >>= 1) {
        ss += __shfl_xor_sync(0xffffffffu, ss, o);
        p  += __shfl_xor_sync(0xffffffffu, p, o);
        q  += __shfl_xor_sync(0xffffffffu, q, o);
    }
    float inv = 1.0f / fmaxf(sqrtf(ss), 1e-12f);
    float* zr = g_Z + (size_t)warp * DD;
#pragma unroll
    for (int k = 0; k < 8; k++) zr[lane + k * 32] = v[k] * inv;
    if (lane == 0) { g_p[warp] = p; g_q[warp] = q; }
}

// edges: score, exp (no max shift — ratio-invariant), segment sum, edge bitmap
__global__ void k_edge12(const void* __restrict__ ei, const float* __restrict__ bsc) {
    int e = blockIdx.x * blockDim.x + threadIdx.x;
    if (e >= EE) return;
    int s = eidx(ei, e), d = eidx(ei, EE + e);
    float x = g_p[s] + g_q[d] + bsc[0];
    x = (x >= 0.f) ? x : 0.01f * x;
    float ex = expf(x);
    g_s[e] = ex;
    atomicAdd(&g_den[s], ex);
    atomicOr(&g_EB[s * NWm + (d >> 5)], 1u << (d & 31));
}
__global__ void k_edge3(const void* __restrict__ ei) {
    int e = blockIdx.x * blockDim.x + threadIdx.x;
    if (e >= EE) return;
    int s = eidx(ei, e), d = eidx(ei, EE + e);
    float att = g_s[e] / g_den[s];
    atomicAdd(&g_att[(size_t)s * NN + d], att);
}

// edge-parallel A1: one thread per edge; exactly-once accumulation via atomicOr
__global__ void k_eA1(const void* __restrict__ ei) {
    int e = blockIdx.x * blockDim.x + threadIdx.x;
    if (e >= EE) return;
    int s = eidx(ei, e), d = eidx(ei, EE + e);
    if (s == d) return;                            // offdiag
    float att = g_att[(size_t)s * NN + d];         // total (all duplicates summed)
    const float4* zs = reinterpret_cast<const float4*>(g_Z + (size_t)s * DD);
    const float4* zd = reinterpret_cast<const float4*>(g_Z + (size_t)d * DD);
    float dot = 0.f;
#pragma unroll 8
    for (int k = 0; k < 64; k++) {
        float4 a = zs[k], b = zd[k];
        dot += a.x * b.x + a.y * b.y + a.z * b.z + a.w * b.w;
    }
    float fit = dot + att;
    if (fit >= 0.1f) {
        unsigned bit = 1u << (d & 31);
        unsigned old = atomicOr(&g_A1[s * NWm + (d >> 5)], bit);
        if (!(old & bit)) {                        // first setter of this position
            atomicAdd(&g_num1[s], fit);
            atomicAdd(&g_deg1[s], 1.f);
        }
    }
}

// A2 = (A1@A1>0)&offdiag&~A1 ; CM ; CMT scatter ; num2 via vector-sum linearity
__global__ __launch_bounds__(128) void k_A2() {
    __shared__ unsigned short nb[NN];              // A1-neighbor list, then A2 list
    __shared__ float zi_s[DD];
    __shared__ float red[128];
    __shared__ int cnt, cnt2;
    int i = blockIdx.x, t = threadIdx.x;
    if (t == 0) { cnt = 0; cnt2 = 0; }
    unsigned rw = g_A1[i * NWm + t];
    for (int k = t; k < DD; k += 128) zi_s[k] = g_Z[(size_t)i * DD + k];
    __syncthreads();
    unsigned tmp = rw;
    while (tmp) {
        int b = __ffs(tmp) - 1; tmp &= tmp - 1;
        int pos = atomicAdd(&cnt, 1);
        nb[pos] = (unsigned short)(t * 32 + b);
    }
    __syncthreads();
    unsigned acc = 0;
    int nc = cnt;
    for (int idx = 0; idx < nc; idx++) acc |= g_A1[(int)nb[idx] * NWm + t];
    unsigned diagm = ((i >> 5) == t) ? (1u << (i & 31)) : 0u;
    unsigned a2 = acc & ~rw & ~diagm;
    g_A2[i * NWm + t] = a2;
    unsigned cm = rw | a2;
    g_CM[i * NWm + t] = cm;
    unsigned word = cm;
    unsigned ibit = 1u << (i & 31);
    int iw = i >> 5;
    while (word) {
        int b = __ffs(word) - 1; word &= word - 1;
        int j = t * 32 + b;
        atomicOr(&g_CMT[j * NWm + iw], ibit);
    }
    __syncthreads();                               // nb free for reuse as A2 list
    unsigned w2 = a2;
    while (w2) {
        int b = __ffs(w2) - 1; w2 &= w2 - 1;
        int pos = atomicAdd(&cnt2, 1);
        nb[pos] = (unsigned short)(t * 32 + b);
    }
    __syncthreads();
    int n2 = cnt2;
    // num2 = Z_i . (sum_j Z_j) + sum_j att_ij   (column-owned accumulation)
    float sx = 0.f, sy = 0.f;
    const float2* Zb = reinterpret_cast<const float2*>(g_Z);
#pragma unroll 4
    for (int idx = 0; idx < n2; idx++) {
        float2 v = Zb[(size_t)nb[idx] * 128 + t];
        sx += v.x; sy += v.y;
    }
    float asum = 0.f;
    for (int idx = t; idx < n2; idx += 128)
        asum += g_att[(size_t)i * NN + nb[idx]];
    red[t] = zi_s[2 * t] * sx + zi_s[2 * t + 1] * sy + asum;
    __syncthreads();
    for (int o = 64; o; o >>= 1) {
        if (t < o) red[t] += red[t + o];
        __syncthreads();
    }
    if (t == 0) {
        float d1 = g_deg1[i];
        float s1 = (d1 > 0.f) ? g_num1[i] / d1 : 0.f;
        float s2 = (n2 > 0) ? red[0] / (float)n2 : 0.f;
        g_scores[i] = 0.5f * (s1 + s2);
    }
}

__global__ void k_mask(float* __restrict__ outMask) {
    int i = (blockIdx.x * blockDim.x + threadIdx.x) >> 5;
    int lane = threadIdx.x & 31;
    if (i >= NN) return;
    float si = g_scores[i];
    bool ok = si > 0.f;
#pragma unroll
    for (int wq = 0; wq < 4; wq++) {
        int w = lane + wq * 32;
        unsigned word = g_A1[i * NWm + w];
        while (word) {
            int b = __ffs(word) - 1; word &= word - 1;
            if (!(si > g_scores[w * 32 + b])) { ok = false; word = 0; }
        }
    }
    ok = __all_sync(0xffffffffu, ok);
    if (lane == 0) { g_mask[i] = ok ? 1 : 0; outMask[i] = ok ? 1.f : 0.f; }
}

// flags + bmoff bits fused (atomicOr; g_bmoff zeroed in k_pre)
__global__ void k_flags() {
    int i = (blockIdx.x * blockDim.x + threadIdx.x) >> 5;
    int lane = threadIdx.x & 31;
    if (i >= NN) return;
    bool red = false;
    int colc = 0;
#pragma unroll
    for (int wq = 0; wq < 4; wq++) {
        int w = lane + wq * 32;
        unsigned cmw = g_CM[i * NWm + w];
        while (cmw) {
            int b = __ffs(cmw) - 1; cmw &= cmw - 1;
            if (g_mask[w * 32 + b]) { red = true; cmw = 0; }
        }
        colc += __popc(g_CMT[i * NWm + w]);
    }
    red = __any_sync(0xffffffffu, red);
#pragma unroll
    for (int o = 16; o; o >>= 1) colc += __shfl_xor_sync(0xffffffffu, colc, o);
    if (lane == 0) {
        bool reduced = red || (colc == 0);
        bool keeping = (!g_mask[i]) && (!reduced);
        g_notkeep[i] = keeping ? 0 : 1;
        g_keep[i]    = reduced ? 0 : 1;
        if (!keeping && !reduced)                      // notkeep && keepcol
            atomicOr(&g_bmoff[i >> 5], 1u << (i & 31));
    }
}

// B = S_w sparse scatter (outB pre-zeroed on forked stream); warp per row
__global__ void k_B(float* __restrict__ outB) {
    int i = (blockIdx.x * blockDim.x + threadIdx.x) >> 5;
    int lane = threadIdx.x & 31;
    if (i >= NN) return;
    float z[8];
    const float* zi = g_Z + (size_t)i * DD;
#pragma unroll
    for (int k = 0; k < 8; k++) z[k] = zi[lane + 32 * k];
#pragma unroll
    for (int wq = 0; wq < 4; wq++) {
        int w = lane + wq * 32;
        unsigned myw = g_CM[i * NWm + w] & g_bmoff[w];
        unsigned act = __ballot_sync(0xffffffffu, myw != 0u);
        while (act) {
            int src = __ffs(act) - 1; act &= act - 1;
            unsigned word = __shfl_sync(0xffffffffu, myw, src);
            int wg = src + wq * 32;
            while (word) {
                int b = __ffs(word) - 1; word &= word - 1;
                int j = wg * 32 + b;
                float fit = wdot(z, j, lane) + g_att[(size_t)i * NN + j];
                if (lane == 0) outB[(size_t)i * NN + j] = fit;
            }
        }
    }
    if (lane == 0) outB[(size_t)i * NN + i] = g_keep[i] ? 1.f : 0.f;
}

// pooled = S_w^T @ emb via CM^T; recomputes fitness (same arithmetic as k_B),
// so it has NO dependence on outB and runs concurrently with it.
__global__ void k_pooled(float* __restrict__ outP, const float* __restrict__ emb) {
    int j = (blockIdx.x * blockDim.x + threadIdx.x) >> 5;
    int lane = threadIdx.x & 31;
    if (j >= NN) return;
    if (!g_keep[j]) {
#pragma unroll
        for (int k = 0; k < 8; k++) outP[(size_t)j * DD + lane + k * 32] = 0.f;
        return;
    }
    float acc[8];
#pragma unroll
    for (int k = 0; k < 8; k++) acc[k] = 0.f;
    if (g_notkeep[j]) {
        float zj[8];
        const float* zr = g_Z + (size_t)j * DD;
#pragma unroll
        for (int k = 0; k < 8; k++) zj[k] = zr[lane + 32 * k];
#pragma unroll
        for (int wq = 0; wq < 4; wq++) {
            int w = lane + wq * 32;
            unsigned myw = g_CMT[j * NWm + w];
            unsigned act = __ballot_sync(0xffffffffu, myw != 0u);
            while (act) {
                int src = __ffs(act) - 1; act &= act - 1;
                unsigned word = __shfl_sync(0xffffffffu, myw, src);
                int wg = src + wq * 32;
                while (word) {
                    int b = __ffs(word) - 1; word &= word - 1;
                    int i2 = wg * 32 + b;
                    float fit = wdot(zj, i2, lane) + g_att[(size_t)i2 * NN + j];
                    const float* er = emb + (size_t)i2 * DD + lane;
#pragma unroll
                    for (int k = 0; k < 8; k++) acc[k] += fit * er[k * 32];
                }
            }
        }
    }
    const float* ej = emb + (size_t)j * DD + lane;
#pragma unroll
    for (int k = 0; k < 8; k++)
        outP[(size_t)j * DD + lane + k * 32] = ej[k * 32] + acc[k];
}

// new_w = S^T EMw S (exact integer f32 adds); adj = 1.0 at nonzeros.
// 256 threads: thread owns half a word (16 R columns) -> 2x parallel vs 128.
__global__ __launch_bounds__(256) void k_neww(float* __restrict__ neww,
                                              float* __restrict__ adj) {
    __shared__ unsigned short nb[NN];
    __shared__ unsigned short al[NN];
    __shared__ unsigned R[NN];
    __shared__ int cnt, acnt;
    int i = blockIdx.x, t = threadIdx.x;
    int w2 = t >> 1, half = t & 1;                 // word, half-word
    if (t == 0) { cnt = 0; acnt = 0; }
#pragma unroll
    for (int c = 0; c < 16; c++) R[w2 * 32 + half * 16 + c] = 0u;
    unsigned erw = 0u, aw = 0u;
    if (t < 128) {
        erw = g_EB[i * NWm + t];
        if ((i >> 5) == t) erw |= 1u << (i & 31);  // EMw has unit diagonal
        aw = g_CM[i * NWm + t] & g_bmoff[t];
        if (((i >> 5) == t) && g_keep[i]) aw |= 1u << (i & 31);
    }
    __syncthreads();
    if (t < 128) {
        unsigned tmp = erw;
        while (tmp) {
            int b = __ffs(tmp) - 1; tmp &= tmp - 1;
            int pos = atomicAdd(&cnt, 1);
            nb[pos] = (unsigned short)(t * 32 + b);
        }
        tmp = aw;
        while (tmp) {
            int b = __ffs(tmp) - 1; tmp &= tmp - 1;
            int pos = atomicAdd(&acnt, 1);
            al[pos] = (unsigned short)(t * 32 + b);
        }
    }
    __syncthreads();
    int nc = cnt, ac = acnt;
    if (ac == 0) return;
    unsigned hmask = 0xFFFFu << (half * 16);
    for (int idx = 0; idx < nc; idx++) {
        int jn = nb[idx];
        unsigned sw = g_CM[jn * NWm + w2] & g_bmoff[w2] & hmask;
        if (((jn >> 5) == w2) && g_keep[jn]) sw |= (1u << (jn & 31)) & hmask;
        while (sw) {
            int b = __ffs(sw) - 1; sw &= sw - 1;
            R[w2 * 32 + b]++;
        }
    }
    unsigned nz = 0;
#pragma unroll
    for (int c = 0; c < 16; c++)
        if (R[w2 * 32 + half * 16 + c]) nz |= 1u << (half * 16 + c);
    for (int ai = 0; ai < ac; ai++) {
        int a = al[ai];
        size_t base = (size_t)a * NN + w2 * 32;
        unsigned m = nz;
        while (m) {
            int c = __ffs(m) - 1; m &= m - 1;
            atomicAdd(&neww[base + c], (float)R[w2 * 32 + c]);
            adj[base + c] = 1.0f;      // same-value race: benign
        }
    }
}

// restore g_att == 0 invariant (precise un-scatter of edge positions)
__global__ void k_clean(const void* __restrict__ ei) {
    int e = blockIdx.x * blockDim.x + threadIdx.x;
    if (e >= EE) return;
    int s = eidx(ei, e), d = eidx(ei, EE + e);
    g_att[(size_t)s * NN + d] = 0.f;
}

// ---------------- launch ------------------------------------------------------
extern "C" void kernel_launch(void* const* d_in, const int* in_sizes, int n_in,
                              void* d_out, int out_size) {
    const float* emb = (const float*)d_in[0];
    const void*  ei  = d_in[1];                 // int32 or int64; sniffed on device
    const float* W   = (const float*)d_in[4];
    const float* bsc = (const float*)d_in[5];

    float* out       = (float*)d_out;
    float* outPooled = out;                                // [N, D]
    float* outAdj    = outPooled + (size_t)NN * DD;        // [N, N]
    float* outW      = outAdj + (size_t)NN * NN;           // [N, N]
    float* outB      = outW + (size_t)NN * NN;             // [N, N]
    float* outMask   = outB + (size_t)NN * NN;             // [N]

    static cudaStream_t s1, s2;
    static cudaEvent_t evRoot, evZ, evF, evB, evN, evC;
    static int inited = 0;
    if (!inited) {
        cudaStreamCreateWithFlags(&s1, cudaStreamNonBlocking);
        cudaStreamCreateWithFlags(&s2, cudaStreamNonBlocking);
        cudaEventCreateWithFlags(&evRoot, cudaEventDisableTiming);
        cudaEventCreateWithFlags(&evZ, cudaEventDisableTiming);
        cudaEventCreateWithFlags(&evF, cudaEventDisableTiming);
        cudaEventCreateWithFlags(&evB, cudaEventDisableTiming);
        cudaEventCreateWithFlags(&evN, cudaEventDisableTiming);
        cudaEventCreateWithFlags(&evC, cudaEventDisableTiming);
        inited = 1;
    }

    // fork: s1 zero-fills outW/outAdj/outB concurrently with the front pipeline
    cudaEventRecord(evRoot, 0);
    cudaStreamWaitEvent(s1, evRoot, 0);
    k_zeroWA<<<16384, 256, 0, s1>>>((float4*)outW, (float4*)outAdj, (float4*)outB);
    cudaEventRecord(evZ, s1);

    // main pipeline (legacy stream)
    k_pre<<<1025, 256>>>(emb, W, (const unsigned*)ei);
    k_edge12<<<EE / 256, 256>>>(ei, bsc);
    k_edge3<<<EE / 256, 256>>>(ei);
    k_eA1<<<EE / 256, 256>>>(ei);
    k_A2<<<NN, 128>>>();
    k_mask<<<NN / 8, 256>>>(outMask);
    k_flags<<<NN / 8, 256>>>();
    cudaEventRecord(evF, 0);

    // s1: neww (needs flags/bmoff + zeroed W/adj), concurrent with B/pooled
    cudaStreamWaitEvent(s1, evF, 0);
    k_neww<<<NN, 256, 0, s1>>>(outW, outAdj);
    cudaEventRecord(evN, s1);

    // s2: pooled (fitness recompute; independent of outB), concurrent with B
    cudaStreamWaitEvent(s2, evF, 0);
    k_pooled<<<NN / 8, 256, 0, s2>>>(outPooled, emb);

    // main: B scatter (needs zeroed outB)
    cudaStreamWaitEvent(0, evZ, 0);
    k_B<<<NN / 8, 256>>>(outB);
    cudaEventRecord(evB, 0);

    // s2 (in-order after pooled): clean att once B's reads are also done
    cudaStreamWaitEvent(s2, evB, 0);
    k_clean<<<EE / 256, 256, 0, s2>>>(ei);
    cudaEventRecord(evC, s2);

    // join everything back to the main stream
    cudaStreamWaitEvent(0, evN, 0);
    cudaStreamWaitEvent(0, evC, 0);
}